// round 15
// baseline (speedup 1.0000x reference)
#include <cuda_runtime.h>
#include <cuda_fp16.h>
#include <cstdint>

// ---------------------------------------------------------------------------
// GINRegressor on GB300: CSR gather (fp16, pairwise HADD2) fused into
// single-product fp16 tensor MLP: D = A * fp16(W).
// 1024 thr/CTA persistent; ping-pong fp16 buffers; pre-scaled CSR offsets;
// layer2 GEMM2 folded to GEMV (w2fc = W2_2 @ fc_w).
// Fast prelude: 16-elem/thread scan, 4-edge/thread fill (int4 loads).
// Launch order: prep(1), scan(2), fill(3), mlp0(4), mlp1(5), mlp2(6), final(7).
// Invariant: cursor/gsum/gcnt zero at entry (final_kernel restores).
// ---------------------------------------------------------------------------

#define NMAX 50000
#define EMAX 800000
#define GMAX 500
#define LDT 136  // padded smem tile stride (fp16 elems) -> conflict-free

__device__ __half g_xh[NMAX * 128];       // fp16 copy of input x
__device__ __half g_bufA[NMAX * 128];
__device__ __half g_bufB[NMAX * 128];
__device__ float g_gsum[GMAX];
__device__ float g_gcnt[GMAX];
__device__ int   g_rowptr[NMAX + 1];
__device__ int   g_cursor[NMAX];          // zero at entry (invariant)
__device__ int   g_csrc[EMAX];            // pre-scaled: src*32 (uint2 rows)
__device__ float g_w2fc[129];             // [0..127]=W2_2@fc, [128]=b2_2.fc
__device__ __align__(16) __half g_wth[6 * 16384];  // W^T fp16 planes

// ---------------- helpers ----------------
__device__ __forceinline__ uint32_t smem_u32(const void* p) {
    uint32_t a;
    asm("{ .reg .u64 t; cvta.to.shared.u64 t, %1; cvt.u32.u64 %0, t; }"
        : "=r"(a) : "l"(p));
    return a;
}

__device__ __forceinline__ void ldm4(uint32_t* a, uint32_t addr) {
    asm volatile("ldmatrix.sync.aligned.m8n8.x4.shared.b16 {%0,%1,%2,%3}, [%4];"
                 : "=r"(a[0]), "=r"(a[1]), "=r"(a[2]), "=r"(a[3]) : "r"(addr));
}

__device__ __forceinline__ void mma16816(float* c, const uint32_t* a,
                                         uint32_t b0, uint32_t b1) {
    asm volatile(
        "mma.sync.aligned.m16n8k16.row.col.f32.f16.f16.f32 "
        "{%0,%1,%2,%3}, {%4,%5,%6,%7}, {%8,%9}, {%0,%1,%2,%3};"
        : "+f"(c[0]), "+f"(c[1]), "+f"(c[2]), "+f"(c[3])
        : "r"(a[0]), "r"(a[1]), "r"(a[2]), "r"(a[3]), "r"(b0), "r"(b1));
}

// ---------------- prep: weights + x->fp16 + edge count + w2fc ----------------
__global__ void prep_kernel(const float* __restrict__ Wa, const float* __restrict__ Wb,
                            const float* __restrict__ Wc, const float* __restrict__ Wd,
                            const float* __restrict__ We, const float* __restrict__ Wf,
                            __half* __restrict__ wt,
                            const float* __restrict__ x, __half* __restrict__ xh, int N,
                            const int* __restrict__ ei, int* __restrict__ cnt, int E,
                            const float* __restrict__ fcw, const float* __restrict__ b2f,
                            float* __restrict__ w2fc) {
    int t = blockIdx.x * blockDim.x + threadIdx.x;
    if (t < 6 * 16384) {
        int m = t >> 14;
        int i = t & 16383;
        int n = i >> 7, k = i & 127;
        const float* W = (m == 0) ? Wa : (m == 1) ? Wb : (m == 2) ? Wc
                       : (m == 3) ? Wd : (m == 4) ? We : Wf;
        wt[t] = __float2half_rn(W[k * 128 + n]);
    } else if (t < 6 * 16384 + 128) {
        int k = t - 6 * 16384;
        float s = 0.f;
        #pragma unroll 4
        for (int c = 0; c < 128; c++) s = fmaf(Wf[k * 128 + c], fcw[c], s);
        w2fc[k] = s;
    } else if (t == 6 * 16384 + 128) {
        float s = 0.f;
        for (int c = 0; c < 128; c++) s = fmaf(b2f[c], fcw[c], s);
        w2fc[128] = s;
    }
    // x -> fp16 (8 elements per thread)
    if (t < N * 16) {
        const float4* x4 = (const float4*)x;
        float4 a = x4[t * 2];
        float4 b = x4[t * 2 + 1];
        uint4 o;
        *(__half2*)&o.x = __floats2half2_rn(a.x, a.y);
        *(__half2*)&o.y = __floats2half2_rn(a.z, a.w);
        *(__half2*)&o.z = __floats2half2_rn(b.x, b.y);
        *(__half2*)&o.w = __floats2half2_rn(b.z, b.w);
        ((uint4*)xh)[t] = o;
    }
    // edge count: 4 edges per thread (overlapped atomics)
    {
        int idx = t * 4;
        if (idx + 3 < E) {
            int4 d4 = *(const int4*)&ei[E + idx];
            atomicAdd(&cnt[d4.x], 1);
            atomicAdd(&cnt[d4.y], 1);
            atomicAdd(&cnt[d4.z], 1);
            atomicAdd(&cnt[d4.w], 1);
        } else if (idx < E) {
            for (int j = idx; j < E; j++) atomicAdd(&cnt[ei[E + j]], 1);
        }
    }
}

// ---------------- CSR build ----------------
#define SCAN_EPT 16
__global__ __launch_bounds__(1024) void scan_kernel(int* __restrict__ cursor,
                                                    int* __restrict__ rowptr, int N) {
    __shared__ int warpsums[32];
    __shared__ int s_carry;
    int tid = threadIdx.x, lane = tid & 31, wid = tid >> 5;
    if (tid == 0) s_carry = 0;
    __syncthreads();
    for (int base = 0; base < N; base += 1024 * SCAN_EPT) {
        int i0 = base + tid * SCAN_EPT;
        int vals[SCAN_EPT];
        int tot = 0;
        #pragma unroll
        for (int j = 0; j < SCAN_EPT; j++) {
            int i = i0 + j;
            vals[j] = (i < N) ? cursor[i] : 0;
            tot += vals[j];
        }
        int x = tot;
        #pragma unroll
        for (int d = 1; d < 32; d <<= 1) {
            int y = __shfl_up_sync(0xffffffffu, x, d);
            if (lane >= d) x += y;
        }
        if (lane == 31) warpsums[wid] = x;
        __syncthreads();
        if (wid == 0) {
            int w = warpsums[lane];
            #pragma unroll
            for (int d = 1; d < 32; d <<= 1) {
                int y = __shfl_up_sync(0xffffffffu, w, d);
                if (lane >= d) w += y;
            }
            warpsums[lane] = w;
        }
        __syncthreads();
        int run = s_carry + ((wid > 0) ? warpsums[wid - 1] : 0) + (x - tot);
        #pragma unroll
        for (int j = 0; j < SCAN_EPT; j++) {
            int i = i0 + j;
            if (i < N) { rowptr[i] = run; cursor[i] = run; }
            run += vals[j];
        }
        __syncthreads();
        if (tid == 0) s_carry += warpsums[31];
        __syncthreads();
    }
    if (threadIdx.x == 0) rowptr[N] = s_carry;
}

// 4 edges per thread, int4 loads, overlapped atomics
__global__ void fill_kernel(const int* __restrict__ ei, int* __restrict__ cursor,
                            int* __restrict__ csrc, int E) {
    int t = blockIdx.x * blockDim.x + threadIdx.x;
    int idx = t * 4;
    if (idx + 3 < E) {
        int4 d4 = *(const int4*)&ei[E + idx];
        int4 s4 = *(const int4*)&ei[idx];
        int p0 = atomicAdd(&cursor[d4.x], 1);
        int p1 = atomicAdd(&cursor[d4.y], 1);
        int p2 = atomicAdd(&cursor[d4.z], 1);
        int p3 = atomicAdd(&cursor[d4.w], 1);
        csrc[p0] = s4.x << 5;
        csrc[p1] = s4.y << 5;
        csrc[p2] = s4.z << 5;
        csrc[p3] = s4.w << 5;
    } else if (idx < E) {
        for (int j = idx; j < E; j++) {
            int d = ei[E + j];
            int p = atomicAdd(&cursor[d], 1);
            csrc[p] = ei[j] << 5;
        }
    }
}

// final output + restore invariants (cursor/gsum/gcnt = 0)
__global__ void final_kernel(float* __restrict__ gsum, float* __restrict__ gcnt,
                             const float* __restrict__ fcb,
                             float* __restrict__ out, int G,
                             int* __restrict__ cursor, int N) {
    int i = blockIdx.x * blockDim.x + threadIdx.x;
    if (i < G) {
        out[i] = gsum[i] / fmaxf(gcnt[i], 1.0f) + fcb[0];
        gsum[i] = 0.f;
        gcnt[i] = 0.f;
    }
    if (i < N) cursor[i] = 0;
}

// ---------------- fused aggregate + MLP (persistent, 1024 thr) ----------------
#define SM_B1  0        // 34816
#define SM_B2  34816
#define SM_A   69632    // single fp16 A plane (also T after epilogue1)
#define SM_SB1 104448
#define SM_SB2 104960
#define SM_SFW 105472
#define SM_SROW 105984
#define SM_TOTAL 106496

// single-product fp16 GEMM: acc += A*B  (per-warp 16x32 tile)
__device__ __forceinline__ void gemm_tile(
    const __half* sA, const __half* sB,
    float acc[4][4], int wr, int wc, int lane) {
    int arow = wr * 16 + (lane & 15);
    int acol = (lane >> 4) * 8;
    int bn = wc * 32 + ((lane >> 4) << 3) + (lane & 7);
    int bk = ((lane >> 3) & 1) << 3;
    const __half* a_base = sA + arow * LDT + acol;
    const __half* b_base = sB + bn * LDT + bk;
    #pragma unroll
    for (int k0 = 0; k0 < 8; k0++) {
        uint32_t a[4];
        ldm4(a, smem_u32(a_base + k0 * 16));
        #pragma unroll
        for (int p = 0; p < 2; p++) {
            int nfp = p * 2;
            uint32_t b[4];
            ldm4(b, smem_u32(b_base + nfp * 8 * LDT + k0 * 16));
            mma16816(acc[nfp],     a, b[0], b[1]);
            mma16816(acc[nfp + 1], a, b[2], b[3]);
        }
    }
}

// accumulate 4 neighbor rows; pairwise fp16 adds, then fp32 accumulation
#define GATHER4H(v, J)                                                    \
    do {                                                                  \
        int o0 = __ldg(&csrc[(J)]);                                       \
        int o1 = __ldg(&csrc[(J) + 1]);                                   \
        int o2 = __ldg(&csrc[(J) + 2]);                                   \
        int o3 = __ldg(&csrc[(J) + 3]);                                   \
        uint2 w0 = Xh[o0 + lane];                                         \
        uint2 w1 = Xh[o1 + lane];                                         \
        uint2 w2 = Xh[o2 + lane];                                         \
        uint2 w3 = Xh[o3 + lane];                                         \
        __half2 p0 = __hadd2(*(__half2*)&w0.x, *(__half2*)&w1.x);         \
        __half2 p1 = __hadd2(*(__half2*)&w0.y, *(__half2*)&w1.y);         \
        __half2 p2 = __hadd2(*(__half2*)&w2.x, *(__half2*)&w3.x);         \
        __half2 p3 = __hadd2(*(__half2*)&w2.y, *(__half2*)&w3.y);         \
        float2 f;                                                         \
        f = __half22float2(p0); v.x += f.x; v.y += f.y;                   \
        f = __half22float2(p2); v.x += f.x; v.y += f.y;                   \
        f = __half22float2(p1); v.z += f.x; v.w += f.y;                   \
        f = __half22float2(p3); v.z += f.x; v.w += f.y;                   \
    } while (0)

__global__ __launch_bounds__(1024, 1) void mlp_kernel(
    const __half* __restrict__ X,
    const int* __restrict__ rowptr, const int* __restrict__ csrc,
    __half* __restrict__ H,
    const __half* __restrict__ W1, const __half* __restrict__ W2,
    const float* __restrict__ b1, const float* __restrict__ b2,
    const float* __restrict__ epsp,
    int n, int ntiles, int relu_out, int pool,
    const int* __restrict__ batch, const float* __restrict__ w2fc,
    float* __restrict__ gsum, float* __restrict__ gcnt) {
    extern __shared__ char sm[];
    __half* sB1 = (__half*)(sm + SM_B1);
    __half* sB2 = (__half*)(sm + SM_B2);
    __half* sA  = (__half*)(sm + SM_A);
    float* sb1  = (float*)(sm + SM_SB1);
    float* sb2  = (float*)(sm + SM_SB2);
    float* sfw  = (float*)(sm + SM_SFW);   // w2fc for pool layer
    float* srow = (float*)(sm + SM_SROW);

    int tid = threadIdx.x;
    int lane = tid & 31;
    int wid = tid >> 5;           // 0..31
    int wr = wid & 7;             // row group (16 rows)
    int wc = wid >> 3;            // col group (32 cols)

    if (tid < 128) {
        sb1[tid] = b1[tid];
        sb2[tid] = b2[tid];
        sfw[tid] = w2fc[tid];
    }

    // load weight planes once (persistent); pool layer skips B2
    {
        const uint4* p1 = (const uint4*)W1;
        const uint4* p2 = (const uint4*)W2;
        for (int i = tid; i < 2048; i += 1024) {
            int r = i >> 4, c = (i & 15) * 8;
            int d = r * LDT + c;
            *(uint4*)&sB1[d] = p1[i];
            if (!pool) *(uint4*)&sB2[d] = p2[i];
        }
    }

    float s = 1.0f + __ldg(epsp);
    float bconst = __ldg(&w2fc[128]);
    const uint2* Xh = (const uint2*)X;

    for (int tile = blockIdx.x; tile < ntiles; tile += gridDim.x) {
        int row0 = tile * 128;
        if (tid < 128) srow[tid] = 0.f;

        // gather: A = (1+eps)*X[row] + sum_nbrs X[j]; 2 rows per warp iter
        for (int r2 = wid; r2 < 64; r2 += 32) {
            int rA = r2, rB = r2 + 64;
            int grA = row0 + rA, grB = row0 + rB;
            float4 va = make_float4(0.f, 0.f, 0.f, 0.f);
            float4 vb = make_float4(0.f, 0.f, 0.f, 0.f);
            int ja = 0, ea = 0, jb = 0, eb = 0;
            if (grA < n) {
                uint2 w = Xh[grA * 32 + lane];
                float2 f0 = __half22float2(*(__half2*)&w.x);
                float2 f1 = __half22float2(*(__half2*)&w.y);
                va.x = s * f0.x; va.y = s * f0.y;
                va.z = s * f1.x; va.w = s * f1.y;
                ja = __ldg(&rowptr[grA]); ea = __ldg(&rowptr[grA + 1]);
            }
            if (grB < n) {
                uint2 w = Xh[grB * 32 + lane];
                float2 f0 = __half22float2(*(__half2*)&w.x);
                float2 f1 = __half22float2(*(__half2*)&w.y);
                vb.x = s * f0.x; vb.y = s * f0.y;
                vb.z = s * f1.x; vb.w = s * f1.y;
                jb = __ldg(&rowptr[grB]); eb = __ldg(&rowptr[grB + 1]);
            }
            while (ja + 4 <= ea && jb + 4 <= eb) {
                GATHER4H(va, ja);
                GATHER4H(vb, jb);
                ja += 4; jb += 4;
            }
            for (; ja + 4 <= ea; ja += 4) GATHER4H(va, ja);
            for (; ja < ea; ja++) {
                int o0 = __ldg(&csrc[ja]);
                uint2 w = Xh[o0 + lane];
                float2 f0 = __half22float2(*(__half2*)&w.x);
                float2 f1 = __half22float2(*(__half2*)&w.y);
                va.x += f0.x; va.y += f0.y; va.z += f1.x; va.w += f1.y;
            }
            for (; jb + 4 <= eb; jb += 4) GATHER4H(vb, jb);
            for (; jb < eb; jb++) {
                int o0 = __ldg(&csrc[jb]);
                uint2 w = Xh[o0 + lane];
                float2 f0 = __half22float2(*(__half2*)&w.x);
                float2 f1 = __half22float2(*(__half2*)&w.y);
                vb.x += f0.x; vb.y += f0.y; vb.z += f1.x; vb.w += f1.y;
            }
            uint2 o;
            *(__half2*)&o.x = __floats2half2_rn(va.x, va.y);
            *(__half2*)&o.y = __floats2half2_rn(va.z, va.w);
            *(uint2*)&sA[rA * LDT + lane * 4] = o;
            *(__half2*)&o.x = __floats2half2_rn(vb.x, vb.y);
            *(__half2*)&o.y = __floats2half2_rn(vb.z, vb.w);
            *(uint2*)&sA[rB * LDT + lane * 4] = o;
        }
        __syncthreads();

        float acc[4][4];
        #pragma unroll
        for (int j = 0; j < 4; j++)
            #pragma unroll
            for (int q = 0; q < 4; q++) acc[j][q] = 0.f;

        // GEMM1
        gemm_tile(sA, sB1, acc, wr, wc, lane);

        if (pool) {
            // layer 2: h.fc = ReLU(acc+b1) @ w2fc (+ bconst per node)
            int r = wr * 16 + (lane >> 2);
            float d0 = 0.f, d1 = 0.f;
            #pragma unroll
            for (int nf = 0; nf < 4; nf++) {
                int c = wc * 32 + nf * 8 + (lane & 3) * 2;
                float* a = acc[nf];
                d0 = fmaf(fmaxf(a[0] + sb1[c], 0.f), sfw[c], d0);
                d0 = fmaf(fmaxf(a[1] + sb1[c + 1], 0.f), sfw[c + 1], d0);
                d1 = fmaf(fmaxf(a[2] + sb1[c], 0.f), sfw[c], d1);
                d1 = fmaf(fmaxf(a[3] + sb1[c + 1], 0.f), sfw[c + 1], d1);
            }
            atomicAdd(&srow[r], d0);
            atomicAdd(&srow[r + 8], d1);
            __syncthreads();
            if (tid < 128) {
                int gr = row0 + tid;
                if (gr < n) {
                    int g = batch[gr];
                    atomicAdd(&gsum[g], srow[tid] + bconst);
                    atomicAdd(&gcnt[g], 1.0f);
                }
            }
            __syncthreads();
            continue;
        }

        __syncthreads();  // all reads of sA done before overwrite

        // epilogue1: T = ReLU(acc + b1) -> fp16 into sA
        {
            int r = wr * 16 + (lane >> 2);
            #pragma unroll
            for (int nf = 0; nf < 4; nf++) {
                int c = wc * 32 + nf * 8 + (lane & 3) * 2;
                float* a = acc[nf];
                float v0 = fmaxf(a[0] + sb1[c], 0.f);
                float v1 = fmaxf(a[1] + sb1[c + 1], 0.f);
                float v2 = fmaxf(a[2] + sb1[c], 0.f);
                float v3 = fmaxf(a[3] + sb1[c + 1], 0.f);
                *(__half2*)&sA[r * LDT + c] = __floats2half2_rn(v0, v1);
                *(__half2*)&sA[(r + 8) * LDT + c] = __floats2half2_rn(v2, v3);
            }
        }
        __syncthreads();

        #pragma unroll
        for (int j = 0; j < 4; j++)
            #pragma unroll
            for (int q = 0; q < 4; q++) acc[j][q] = 0.f;

        // GEMM2
        gemm_tile(sA, sB2, acc, wr, wc, lane);

        // epilogue2: out = acc + b2 (+ReLU) -> H (fp16)
        {
            int r = wr * 16 + (lane >> 2);
            int gr0 = row0 + r, gr1 = gr0 + 8;
            #pragma unroll
            for (int nf = 0; nf < 4; nf++) {
                int c = wc * 32 + nf * 8 + (lane & 3) * 2;
                float* a = acc[nf];
                float v0 = a[0] + sb2[c], v1 = a[1] + sb2[c + 1];
                float v2 = a[2] + sb2[c], v3 = a[3] + sb2[c + 1];
                if (relu_out) {
                    v0 = fmaxf(v0, 0.f); v1 = fmaxf(v1, 0.f);
                    v2 = fmaxf(v2, 0.f); v3 = fmaxf(v3, 0.f);
                }
                if (gr0 < n)
                    *(__half2*)&H[(size_t)gr0 * 128 + c] = __floats2half2_rn(v0, v1);
                if (gr1 < n)
                    *(__half2*)&H[(size_t)gr1 * 128 + c] = __floats2half2_rn(v2, v3);
            }
        }
        __syncthreads();  // protect sA before next tile's gather
    }
}

// ---------------- host launcher ----------------
extern "C" void kernel_launch(void* const* d_in, const int* in_sizes, int n_in,
                              void* d_out, int out_size) {
    const float* x     = (const float*)d_in[0];
    const int*   ei    = (const int*)d_in[1];
    const int*   batch = (const int*)d_in[2];
    const float* W1s[3] = {(const float*)d_in[3],  (const float*)d_in[8],  (const float*)d_in[13]};
    const float* b1s[3] = {(const float*)d_in[4],  (const float*)d_in[9],  (const float*)d_in[14]};
    const float* W2s[3] = {(const float*)d_in[5],  (const float*)d_in[10], (const float*)d_in[15]};
    const float* b2s[3] = {(const float*)d_in[6],  (const float*)d_in[11], (const float*)d_in[16]};
    const float* epss[3]= {(const float*)d_in[7],  (const float*)d_in[12], (const float*)d_in[17]};
    const float* fcw   = (const float*)d_in[18];
    const float* fcb   = (const float*)d_in[19];

    int N = in_sizes[2];
    int E = in_sizes[1] / 2;
    int G = out_size;

    float *gsum, *gcnt, *w2fc;
    __half *xh, *bufA, *bufB, *wth;
    int *rowptr, *cursor, *csrc;
    cudaGetSymbolAddress((void**)&xh,   g_xh);
    cudaGetSymbolAddress((void**)&bufA, g_bufA);
    cudaGetSymbolAddress((void**)&bufB, g_bufB);
    cudaGetSymbolAddress((void**)&gsum, g_gsum);
    cudaGetSymbolAddress((void**)&gcnt, g_gcnt);
    cudaGetSymbolAddress((void**)&rowptr, g_rowptr);
    cudaGetSymbolAddress((void**)&cursor, g_cursor);
    cudaGetSymbolAddress((void**)&csrc, g_csrc);
    cudaGetSymbolAddress((void**)&w2fc, g_w2fc);
    cudaGetSymbolAddress((void**)&wth,  g_wth);

    cudaFuncSetAttribute(mlp_kernel, cudaFuncAttributeMaxDynamicSharedMemorySize, SM_TOTAL);

    int prep_threads = N * 16;                       // covers x conversion
    if ((E + 3) / 4 > prep_threads) prep_threads = (E + 3) / 4;
    if (6 * 16384 + 129 > prep_threads) prep_threads = 6 * 16384 + 129;
    // 1: weight transform + x->fp16 + edge count + w2fc (cursor==0 at entry)
    prep_kernel<<<(prep_threads + 255) / 256, 256>>>(
        W1s[0], W2s[0], W1s[1], W2s[1], W1s[2], W2s[2],
        wth, x, xh, N, ei, cursor, E, fcw, b2s[2], w2fc);
    // 2-3: CSR scan + fill (pre-scaled offsets)
    scan_kernel<<<1, 1024>>>(cursor, rowptr, N);
    fill_kernel<<<((E + 3) / 4 + 255) / 256, 256>>>(ei, cursor, csrc, E);

    // 4-6: ping-pong layers (fp16 everywhere); layer2 pools (no GEMM2)
    const __half* ins[3]  = {xh, bufA, bufB};
    __half*       outs[3] = {bufA, bufB, bufA /* unused (pool) */};
    int ntiles = (N + 127) / 128;
    for (int l = 0; l < 3; l++) {
        mlp_kernel<<<148, 1024, SM_TOTAL>>>(
            ins[l], rowptr, csrc, outs[l],
            wth + (2 * l) * 16384, wth + (2 * l + 1) * 16384,
            b1s[l], b2s[l], epss[l],
            N, ntiles, (l < 2) ? 1 : 0, (l == 2) ? 1 : 0,
            batch, w2fc, gsum, gcnt);
    }
    // 7: output + restore invariants
    final_kernel<<<(N + 255) / 256, 256>>>(gsum, gcnt, fcb, (float*)d_out, G, cursor, N);
}

// round 16
// speedup vs baseline: 1.1605x; 1.1605x over previous
#include <cuda_runtime.h>
#include <cuda_fp16.h>
#include <cstdint>

// ---------------------------------------------------------------------------
// GINRegressor on GB300: CSR gather (fp16, pairwise HADD2) fused into
// single-product fp16 tensor MLP: D = A * fp16(W).
// 1024 thr/CTA persistent; ping-pong fp16 buffers; pre-scaled CSR offsets;
// layer2 GEMM2 folded to GEMV (w2fc = W2_2 @ fc_w).
// Prelude: R13 versions (1-edge/thread count/fill, 1-elem/thread scan) —
// measured faster than R14's batched variants.
// Launch order: prep(1), scan(2), fill(3), mlp0(4), mlp1(5), mlp2(6), final(7).
// Invariant: cursor/gsum/gcnt zero at entry (final_kernel restores).
// ---------------------------------------------------------------------------

#define NMAX 50000
#define EMAX 800000
#define GMAX 500
#define LDT 136  // padded smem tile stride (fp16 elems) -> conflict-free

__device__ __half g_xh[NMAX * 128];       // fp16 copy of input x
__device__ __half g_bufA[NMAX * 128];
__device__ __half g_bufB[NMAX * 128];
__device__ float g_gsum[GMAX];
__device__ float g_gcnt[GMAX];
__device__ int   g_rowptr[NMAX + 1];
__device__ int   g_cursor[NMAX];          // zero at entry (invariant)
__device__ int   g_csrc[EMAX];            // pre-scaled: src*32 (uint2 rows)
__device__ float g_w2fc[129];             // [0..127]=W2_2@fc, [128]=b2_2.fc
__device__ __align__(16) __half g_wth[6 * 16384];  // W^T fp16 planes

// ---------------- helpers ----------------
__device__ __forceinline__ uint32_t smem_u32(const void* p) {
    uint32_t a;
    asm("{ .reg .u64 t; cvta.to.shared.u64 t, %1; cvt.u32.u64 %0, t; }"
        : "=r"(a) : "l"(p));
    return a;
}

__device__ __forceinline__ void ldm4(uint32_t* a, uint32_t addr) {
    asm volatile("ldmatrix.sync.aligned.m8n8.x4.shared.b16 {%0,%1,%2,%3}, [%4];"
                 : "=r"(a[0]), "=r"(a[1]), "=r"(a[2]), "=r"(a[3]) : "r"(addr));
}

__device__ __forceinline__ void mma16816(float* c, const uint32_t* a,
                                         uint32_t b0, uint32_t b1) {
    asm volatile(
        "mma.sync.aligned.m16n8k16.row.col.f32.f16.f16.f32 "
        "{%0,%1,%2,%3}, {%4,%5,%6,%7}, {%8,%9}, {%0,%1,%2,%3};"
        : "+f"(c[0]), "+f"(c[1]), "+f"(c[2]), "+f"(c[3])
        : "r"(a[0]), "r"(a[1]), "r"(a[2]), "r"(a[3]), "r"(b0), "r"(b1));
}

// ---------------- prep: weights + x->fp16 + edge count + w2fc ----------------
__global__ void prep_kernel(const float* __restrict__ Wa, const float* __restrict__ Wb,
                            const float* __restrict__ Wc, const float* __restrict__ Wd,
                            const float* __restrict__ We, const float* __restrict__ Wf,
                            __half* __restrict__ wt,
                            const float* __restrict__ x, __half* __restrict__ xh, int N,
                            const int* __restrict__ ei, int* __restrict__ cnt, int E,
                            const float* __restrict__ fcw, const float* __restrict__ b2f,
                            float* __restrict__ w2fc) {
    int t = blockIdx.x * blockDim.x + threadIdx.x;
    if (t < 6 * 16384) {
        int m = t >> 14;
        int i = t & 16383;
        int n = i >> 7, k = i & 127;
        const float* W = (m == 0) ? Wa : (m == 1) ? Wb : (m == 2) ? Wc
                       : (m == 3) ? Wd : (m == 4) ? We : Wf;
        wt[t] = __float2half_rn(W[k * 128 + n]);
    } else if (t < 6 * 16384 + 128) {
        int k = t - 6 * 16384;
        float s = 0.f;
        #pragma unroll 4
        for (int c = 0; c < 128; c++) s = fmaf(Wf[k * 128 + c], fcw[c], s);
        w2fc[k] = s;
    } else if (t == 6 * 16384 + 128) {
        float s = 0.f;
        for (int c = 0; c < 128; c++) s = fmaf(b2f[c], fcw[c], s);
        w2fc[128] = s;
    }
    // x -> fp16 (8 elements per thread)
    if (t < N * 16) {
        const float4* x4 = (const float4*)x;
        float4 a = x4[t * 2];
        float4 b = x4[t * 2 + 1];
        uint4 o;
        *(__half2*)&o.x = __floats2half2_rn(a.x, a.y);
        *(__half2*)&o.y = __floats2half2_rn(a.z, a.w);
        *(__half2*)&o.z = __floats2half2_rn(b.x, b.y);
        *(__half2*)&o.w = __floats2half2_rn(b.z, b.w);
        ((uint4*)xh)[t] = o;
    }
    if (t < E) atomicAdd(&cnt[ei[E + t]], 1);
}

// ---------------- CSR build ----------------
__global__ __launch_bounds__(1024) void scan_kernel(int* __restrict__ cursor,
                                                    int* __restrict__ rowptr, int N) {
    __shared__ int warpsums[32];
    __shared__ int s_carry;
    int tid = threadIdx.x, lane = tid & 31, wid = tid >> 5;
    if (tid == 0) s_carry = 0;
    __syncthreads();
    for (int base = 0; base < N; base += 1024) {
        int i = base + tid;
        int v = (i < N) ? cursor[i] : 0;
        int x = v;
        #pragma unroll
        for (int d = 1; d < 32; d <<= 1) {
            int y = __shfl_up_sync(0xffffffffu, x, d);
            if (lane >= d) x += y;
        }
        if (lane == 31) warpsums[wid] = x;
        __syncthreads();
        if (wid == 0) {
            int w = warpsums[lane];
            #pragma unroll
            for (int d = 1; d < 32; d <<= 1) {
                int y = __shfl_up_sync(0xffffffffu, w, d);
                if (lane >= d) w += y;
            }
            warpsums[lane] = w;
        }
        __syncthreads();
        int excl = x - v + ((wid > 0) ? warpsums[wid - 1] : 0) + s_carry;
        if (i < N) { rowptr[i] = excl; cursor[i] = excl; }
        __syncthreads();
        if (tid == 0) s_carry += warpsums[31];
        __syncthreads();
    }
    if (threadIdx.x == 0) rowptr[N] = s_carry;
}

__global__ void fill_kernel(const int* __restrict__ ei, int* __restrict__ cursor,
                            int* __restrict__ csrc, int E) {
    int t = blockIdx.x * blockDim.x + threadIdx.x;
    if (t < E) {
        int d = ei[E + t];
        int p = atomicAdd(&cursor[d], 1);
        csrc[p] = ei[t] << 5;   // pre-scale: row offset in uint2 units
    }
}

// final output + restore invariants (cursor/gsum/gcnt = 0)
__global__ void final_kernel(float* __restrict__ gsum, float* __restrict__ gcnt,
                             const float* __restrict__ fcb,
                             float* __restrict__ out, int G,
                             int* __restrict__ cursor, int N) {
    int i = blockIdx.x * blockDim.x + threadIdx.x;
    if (i < G) {
        out[i] = gsum[i] / fmaxf(gcnt[i], 1.0f) + fcb[0];
        gsum[i] = 0.f;
        gcnt[i] = 0.f;
    }
    if (i < N) cursor[i] = 0;
}

// ---------------- fused aggregate + MLP (persistent, 1024 thr) ----------------
#define SM_B1  0        // 34816
#define SM_B2  34816
#define SM_A   69632    // single fp16 A plane (also T after epilogue1)
#define SM_SB1 104448
#define SM_SB2 104960
#define SM_SFW 105472
#define SM_SROW 105984
#define SM_TOTAL 106496

// single-product fp16 GEMM: acc += A*B  (per-warp 16x32 tile)
__device__ __forceinline__ void gemm_tile(
    const __half* sA, const __half* sB,
    float acc[4][4], int wr, int wc, int lane) {
    int arow = wr * 16 + (lane & 15);
    int acol = (lane >> 4) * 8;
    int bn = wc * 32 + ((lane >> 4) << 3) + (lane & 7);
    int bk = ((lane >> 3) & 1) << 3;
    const __half* a_base = sA + arow * LDT + acol;
    const __half* b_base = sB + bn * LDT + bk;
    #pragma unroll
    for (int k0 = 0; k0 < 8; k0++) {
        uint32_t a[4];
        ldm4(a, smem_u32(a_base + k0 * 16));
        #pragma unroll
        for (int p = 0; p < 2; p++) {
            int nfp = p * 2;
            uint32_t b[4];
            ldm4(b, smem_u32(b_base + nfp * 8 * LDT + k0 * 16));
            mma16816(acc[nfp],     a, b[0], b[1]);
            mma16816(acc[nfp + 1], a, b[2], b[3]);
        }
    }
}

// accumulate 4 neighbor rows; pairwise fp16 adds, then fp32 accumulation
#define GATHER4H(v, J)                                                    \
    do {                                                                  \
        int o0 = __ldg(&csrc[(J)]);                                       \
        int o1 = __ldg(&csrc[(J) + 1]);                                   \
        int o2 = __ldg(&csrc[(J) + 2]);                                   \
        int o3 = __ldg(&csrc[(J) + 3]);                                   \
        uint2 w0 = Xh[o0 + lane];                                         \
        uint2 w1 = Xh[o1 + lane];                                         \
        uint2 w2 = Xh[o2 + lane];                                         \
        uint2 w3 = Xh[o3 + lane];                                         \
        __half2 p0 = __hadd2(*(__half2*)&w0.x, *(__half2*)&w1.x);         \
        __half2 p1 = __hadd2(*(__half2*)&w0.y, *(__half2*)&w1.y);         \
        __half2 p2 = __hadd2(*(__half2*)&w2.x, *(__half2*)&w3.x);         \
        __half2 p3 = __hadd2(*(__half2*)&w2.y, *(__half2*)&w3.y);         \
        float2 f;                                                         \
        f = __half22float2(p0); v.x += f.x; v.y += f.y;                   \
        f = __half22float2(p2); v.x += f.x; v.y += f.y;                   \
        f = __half22float2(p1); v.z += f.x; v.w += f.y;                   \
        f = __half22float2(p3); v.z += f.x; v.w += f.y;                   \
    } while (0)

__global__ __launch_bounds__(1024, 1) void mlp_kernel(
    const __half* __restrict__ X,
    const int* __restrict__ rowptr, const int* __restrict__ csrc,
    __half* __restrict__ H,
    const __half* __restrict__ W1, const __half* __restrict__ W2,
    const float* __restrict__ b1, const float* __restrict__ b2,
    const float* __restrict__ epsp,
    int n, int ntiles, int relu_out, int pool,
    const int* __restrict__ batch, const float* __restrict__ w2fc,
    float* __restrict__ gsum, float* __restrict__ gcnt) {
    extern __shared__ char sm[];
    __half* sB1 = (__half*)(sm + SM_B1);
    __half* sB2 = (__half*)(sm + SM_B2);
    __half* sA  = (__half*)(sm + SM_A);
    float* sb1  = (float*)(sm + SM_SB1);
    float* sb2  = (float*)(sm + SM_SB2);
    float* sfw  = (float*)(sm + SM_SFW);   // w2fc for pool layer
    float* srow = (float*)(sm + SM_SROW);

    int tid = threadIdx.x;
    int lane = tid & 31;
    int wid = tid >> 5;           // 0..31
    int wr = wid & 7;             // row group (16 rows)
    int wc = wid >> 3;            // col group (32 cols)

    if (tid < 128) {
        sb1[tid] = b1[tid];
        sb2[tid] = b2[tid];
        sfw[tid] = w2fc[tid];
    }

    // load weight planes once (persistent); pool layer skips B2
    {
        const uint4* p1 = (const uint4*)W1;
        const uint4* p2 = (const uint4*)W2;
        for (int i = tid; i < 2048; i += 1024) {
            int r = i >> 4, c = (i & 15) * 8;
            int d = r * LDT + c;
            *(uint4*)&sB1[d] = p1[i];
            if (!pool) *(uint4*)&sB2[d] = p2[i];
        }
    }

    float s = 1.0f + __ldg(epsp);
    float bconst = __ldg(&w2fc[128]);
    const uint2* Xh = (const uint2*)X;

    for (int tile = blockIdx.x; tile < ntiles; tile += gridDim.x) {
        int row0 = tile * 128;
        if (tid < 128) srow[tid] = 0.f;

        // gather: A = (1+eps)*X[row] + sum_nbrs X[j]; 2 rows per warp iter
        for (int r2 = wid; r2 < 64; r2 += 32) {
            int rA = r2, rB = r2 + 64;
            int grA = row0 + rA, grB = row0 + rB;
            float4 va = make_float4(0.f, 0.f, 0.f, 0.f);
            float4 vb = make_float4(0.f, 0.f, 0.f, 0.f);
            int ja = 0, ea = 0, jb = 0, eb = 0;
            if (grA < n) {
                uint2 w = Xh[grA * 32 + lane];
                float2 f0 = __half22float2(*(__half2*)&w.x);
                float2 f1 = __half22float2(*(__half2*)&w.y);
                va.x = s * f0.x; va.y = s * f0.y;
                va.z = s * f1.x; va.w = s * f1.y;
                ja = __ldg(&rowptr[grA]); ea = __ldg(&rowptr[grA + 1]);
            }
            if (grB < n) {
                uint2 w = Xh[grB * 32 + lane];
                float2 f0 = __half22float2(*(__half2*)&w.x);
                float2 f1 = __half22float2(*(__half2*)&w.y);
                vb.x = s * f0.x; vb.y = s * f0.y;
                vb.z = s * f1.x; vb.w = s * f1.y;
                jb = __ldg(&rowptr[grB]); eb = __ldg(&rowptr[grB + 1]);
            }
            while (ja + 4 <= ea && jb + 4 <= eb) {
                GATHER4H(va, ja);
                GATHER4H(vb, jb);
                ja += 4; jb += 4;
            }
            for (; ja + 4 <= ea; ja += 4) GATHER4H(va, ja);
            for (; ja < ea; ja++) {
                int o0 = __ldg(&csrc[ja]);
                uint2 w = Xh[o0 + lane];
                float2 f0 = __half22float2(*(__half2*)&w.x);
                float2 f1 = __half22float2(*(__half2*)&w.y);
                va.x += f0.x; va.y += f0.y; va.z += f1.x; va.w += f1.y;
            }
            for (; jb + 4 <= eb; jb += 4) GATHER4H(vb, jb);
            for (; jb < eb; jb++) {
                int o0 = __ldg(&csrc[jb]);
                uint2 w = Xh[o0 + lane];
                float2 f0 = __half22float2(*(__half2*)&w.x);
                float2 f1 = __half22float2(*(__half2*)&w.y);
                vb.x += f0.x; vb.y += f0.y; vb.z += f1.x; vb.w += f1.y;
            }
            uint2 o;
            *(__half2*)&o.x = __floats2half2_rn(va.x, va.y);
            *(__half2*)&o.y = __floats2half2_rn(va.z, va.w);
            *(uint2*)&sA[rA * LDT + lane * 4] = o;
            *(__half2*)&o.x = __floats2half2_rn(vb.x, vb.y);
            *(__half2*)&o.y = __floats2half2_rn(vb.z, vb.w);
            *(uint2*)&sA[rB * LDT + lane * 4] = o;
        }
        __syncthreads();

        float acc[4][4];
        #pragma unroll
        for (int j = 0; j < 4; j++)
            #pragma unroll
            for (int q = 0; q < 4; q++) acc[j][q] = 0.f;

        // GEMM1
        gemm_tile(sA, sB1, acc, wr, wc, lane);

        if (pool) {
            // layer 2: h.fc = ReLU(acc+b1) @ w2fc (+ bconst per node)
            int r = wr * 16 + (lane >> 2);
            float d0 = 0.f, d1 = 0.f;
            #pragma unroll
            for (int nf = 0; nf < 4; nf++) {
                int c = wc * 32 + nf * 8 + (lane & 3) * 2;
                float* a = acc[nf];
                d0 = fmaf(fmaxf(a[0] + sb1[c], 0.f), sfw[c], d0);
                d0 = fmaf(fmaxf(a[1] + sb1[c + 1], 0.f), sfw[c + 1], d0);
                d1 = fmaf(fmaxf(a[2] + sb1[c], 0.f), sfw[c], d1);
                d1 = fmaf(fmaxf(a[3] + sb1[c + 1], 0.f), sfw[c + 1], d1);
            }
            atomicAdd(&srow[r], d0);
            atomicAdd(&srow[r + 8], d1);
            __syncthreads();
            if (tid < 128) {
                int gr = row0 + tid;
                if (gr < n) {
                    int g = batch[gr];
                    atomicAdd(&gsum[g], srow[tid] + bconst);
                    atomicAdd(&gcnt[g], 1.0f);
                }
            }
            __syncthreads();
            continue;
        }

        __syncthreads();  // all reads of sA done before overwrite

        // epilogue1: T = ReLU(acc + b1) -> fp16 into sA
        {
            int r = wr * 16 + (lane >> 2);
            #pragma unroll
            for (int nf = 0; nf < 4; nf++) {
                int c = wc * 32 + nf * 8 + (lane & 3) * 2;
                float* a = acc[nf];
                float v0 = fmaxf(a[0] + sb1[c], 0.f);
                float v1 = fmaxf(a[1] + sb1[c + 1], 0.f);
                float v2 = fmaxf(a[2] + sb1[c], 0.f);
                float v3 = fmaxf(a[3] + sb1[c + 1], 0.f);
                *(__half2*)&sA[r * LDT + c] = __floats2half2_rn(v0, v1);
                *(__half2*)&sA[(r + 8) * LDT + c] = __floats2half2_rn(v2, v3);
            }
        }
        __syncthreads();

        #pragma unroll
        for (int j = 0; j < 4; j++)
            #pragma unroll
            for (int q = 0; q < 4; q++) acc[j][q] = 0.f;

        // GEMM2
        gemm_tile(sA, sB2, acc, wr, wc, lane);

        // epilogue2: out = acc + b2 (+ReLU) -> H (fp16)
        {
            int r = wr * 16 + (lane >> 2);
            int gr0 = row0 + r, gr1 = gr0 + 8;
            #pragma unroll
            for (int nf = 0; nf < 4; nf++) {
                int c = wc * 32 + nf * 8 + (lane & 3) * 2;
                float* a = acc[nf];
                float v0 = a[0] + sb2[c], v1 = a[1] + sb2[c + 1];
                float v2 = a[2] + sb2[c], v3 = a[3] + sb2[c + 1];
                if (relu_out) {
                    v0 = fmaxf(v0, 0.f); v1 = fmaxf(v1, 0.f);
                    v2 = fmaxf(v2, 0.f); v3 = fmaxf(v3, 0.f);
                }
                if (gr0 < n)
                    *(__half2*)&H[(size_t)gr0 * 128 + c] = __floats2half2_rn(v0, v1);
                if (gr1 < n)
                    *(__half2*)&H[(size_t)gr1 * 128 + c] = __floats2half2_rn(v2, v3);
            }
        }
        __syncthreads();  // protect sA before next tile's gather
    }
}

// ---------------- host launcher ----------------
extern "C" void kernel_launch(void* const* d_in, const int* in_sizes, int n_in,
                              void* d_out, int out_size) {
    const float* x     = (const float*)d_in[0];
    const int*   ei    = (const int*)d_in[1];
    const int*   batch = (const int*)d_in[2];
    const float* W1s[3] = {(const float*)d_in[3],  (const float*)d_in[8],  (const float*)d_in[13]};
    const float* b1s[3] = {(const float*)d_in[4],  (const float*)d_in[9],  (const float*)d_in[14]};
    const float* W2s[3] = {(const float*)d_in[5],  (const float*)d_in[10], (const float*)d_in[15]};
    const float* b2s[3] = {(const float*)d_in[6],  (const float*)d_in[11], (const float*)d_in[16]};
    const float* epss[3]= {(const float*)d_in[7],  (const float*)d_in[12], (const float*)d_in[17]};
    const float* fcw   = (const float*)d_in[18];
    const float* fcb   = (const float*)d_in[19];

    int N = in_sizes[2];
    int E = in_sizes[1] / 2;
    int G = out_size;

    float *gsum, *gcnt, *w2fc;
    __half *xh, *bufA, *bufB, *wth;
    int *rowptr, *cursor, *csrc;
    cudaGetSymbolAddress((void**)&xh,   g_xh);
    cudaGetSymbolAddress((void**)&bufA, g_bufA);
    cudaGetSymbolAddress((void**)&bufB, g_bufB);
    cudaGetSymbolAddress((void**)&gsum, g_gsum);
    cudaGetSymbolAddress((void**)&gcnt, g_gcnt);
    cudaGetSymbolAddress((void**)&rowptr, g_rowptr);
    cudaGetSymbolAddress((void**)&cursor, g_cursor);
    cudaGetSymbolAddress((void**)&csrc, g_csrc);
    cudaGetSymbolAddress((void**)&w2fc, g_w2fc);
    cudaGetSymbolAddress((void**)&wth,  g_wth);

    cudaFuncSetAttribute(mlp_kernel, cudaFuncAttributeMaxDynamicSharedMemorySize, SM_TOTAL);

    int prep_threads = E;
    if (N * 16 > prep_threads) prep_threads = N * 16;
    if (6 * 16384 + 129 > prep_threads) prep_threads = 6 * 16384 + 129;
    // 1: weight transform + x->fp16 + edge count + w2fc (cursor==0 at entry)
    prep_kernel<<<(prep_threads + 255) / 256, 256>>>(
        W1s[0], W2s[0], W1s[1], W2s[1], W1s[2], W2s[2],
        wth, x, xh, N, ei, cursor, E, fcw, b2s[2], w2fc);
    // 2-3: CSR scan + fill (pre-scaled offsets)
    scan_kernel<<<1, 1024>>>(cursor, rowptr, N);
    fill_kernel<<<(E + 255) / 256, 256>>>(ei, cursor, csrc, E);

    // 4-6: ping-pong layers (fp16 everywhere); layer2 pools (no GEMM2)
    const __half* ins[3]  = {xh, bufA, bufB};
    __half*       outs[3] = {bufA, bufB, bufA /* unused (pool) */};
    int ntiles = (N + 127) / 128;
    for (int l = 0; l < 3; l++) {
        mlp_kernel<<<148, 1024, SM_TOTAL>>>(
            ins[l], rowptr, csrc, outs[l],
            wth + (2 * l) * 16384, wth + (2 * l + 1) * 16384,
            b1s[l], b2s[l], epss[l],
            N, ntiles, (l < 2) ? 1 : 0, (l == 2) ? 1 : 0,
            batch, w2fc, gsum, gcnt);
    }
    // 7: output + restore invariants
    final_kernel<<<(N + 255) / 256, 256>>>(gsum, gcnt, fcb, (float*)d_out, G, cursor, N);
}

// round 17
// speedup vs baseline: 1.2549x; 1.0814x over previous
#include <cuda_runtime.h>
#include <cuda_fp16.h>
#include <cstdint>

// ---------------------------------------------------------------------------
// GINRegressor on GB300: CSR gather (fp16, pairwise HADD2) fused into
// single-product fp16 tensor MLP; ALL 3 layers fused into one persistent
// kernel with software grid barriers (148 CTAs, all resident).
// Launch order: prep(1), scan(2), fill(3), mega(4), final(5).
// Invariant: cursor/gsum/gcnt/gridbar zero at entry (final_kernel restores).
// ---------------------------------------------------------------------------

#define NMAX 50000
#define EMAX 800000
#define GMAX 500
#define LDT 136  // padded smem tile stride (fp16 elems) -> conflict-free

__device__ __half g_xh[NMAX * 128];       // fp16 copy of input x
__device__ __half g_bufA[NMAX * 128];
__device__ __half g_bufB[NMAX * 128];
__device__ float g_gsum[GMAX];
__device__ float g_gcnt[GMAX];
__device__ __align__(16) int g_rowptr[NMAX + 4];
__device__ __align__(16) int g_cursor[NMAX + 4];  // zero at entry (invariant)
__device__ int   g_csrc[EMAX];            // pre-scaled: src*32 (uint2 rows)
__device__ float g_w2fc[129];             // [0..127]=W2_2@fc, [128]=b2_2.fc
__device__ int   g_gridbar[2];            // zero at entry (invariant)
__device__ __align__(16) __half g_wth[6 * 16384];  // W^T fp16 planes

// ---------------- helpers ----------------
__device__ __forceinline__ uint32_t smem_u32(const void* p) {
    uint32_t a;
    asm("{ .reg .u64 t; cvta.to.shared.u64 t, %1; cvt.u32.u64 %0, t; }"
        : "=r"(a) : "l"(p));
    return a;
}

__device__ __forceinline__ void ldm4(uint32_t* a, uint32_t addr) {
    asm volatile("ldmatrix.sync.aligned.m8n8.x4.shared.b16 {%0,%1,%2,%3}, [%4];"
                 : "=r"(a[0]), "=r"(a[1]), "=r"(a[2]), "=r"(a[3]) : "r"(addr));
}

__device__ __forceinline__ void mma16816(float* c, const uint32_t* a,
                                         uint32_t b0, uint32_t b1) {
    asm volatile(
        "mma.sync.aligned.m16n8k16.row.col.f32.f16.f16.f32 "
        "{%0,%1,%2,%3}, {%4,%5,%6,%7}, {%8,%9}, {%0,%1,%2,%3};"
        : "+f"(c[0]), "+f"(c[1]), "+f"(c[2]), "+f"(c[3])
        : "r"(a[0]), "r"(a[1]), "r"(a[2]), "r"(a[3]), "r"(b0), "r"(b1));
}

// grid-wide barrier: all gridDim.x CTAs resident (1 CTA/SM enforced by
// smem+regs). Counters are NOT reset here; final_kernel restores them.
__device__ __forceinline__ void grid_barrier(int idx) {
    __syncthreads();
    if (threadIdx.x == 0) {
        __threadfence();
        atomicAdd(&g_gridbar[idx], 1);
        while (*(volatile int*)&g_gridbar[idx] < (int)gridDim.x) {}
        __threadfence();
    }
    __syncthreads();
}

// ---------------- prep: weights + x->fp16 + edge count + w2fc ----------------
__global__ void prep_kernel(const float* __restrict__ Wa, const float* __restrict__ Wb,
                            const float* __restrict__ Wc, const float* __restrict__ Wd,
                            const float* __restrict__ We, const float* __restrict__ Wf,
                            __half* __restrict__ wt,
                            const float* __restrict__ x, __half* __restrict__ xh, int N,
                            const int* __restrict__ ei, int* __restrict__ cnt, int E,
                            const float* __restrict__ fcw, const float* __restrict__ b2f,
                            float* __restrict__ w2fc) {
    int t = blockIdx.x * blockDim.x + threadIdx.x;
    if (t < 6 * 16384) {
        int m = t >> 14;
        int i = t & 16383;
        int n = i >> 7, k = i & 127;
        const float* W = (m == 0) ? Wa : (m == 1) ? Wb : (m == 2) ? Wc
                       : (m == 3) ? Wd : (m == 4) ? We : Wf;
        wt[t] = __float2half_rn(W[k * 128 + n]);
    } else if (t < 6 * 16384 + 128) {
        int k = t - 6 * 16384;
        float s = 0.f;
        #pragma unroll 4
        for (int c = 0; c < 128; c++) s = fmaf(Wf[k * 128 + c], fcw[c], s);
        w2fc[k] = s;
    } else if (t == 6 * 16384 + 128) {
        float s = 0.f;
        for (int c = 0; c < 128; c++) s = fmaf(b2f[c], fcw[c], s);
        w2fc[128] = s;
    }
    // x -> fp16 (8 elements per thread)
    if (t < N * 16) {
        const float4* x4 = (const float4*)x;
        float4 a = x4[t * 2];
        float4 b = x4[t * 2 + 1];
        uint4 o;
        *(__half2*)&o.x = __floats2half2_rn(a.x, a.y);
        *(__half2*)&o.y = __floats2half2_rn(a.z, a.w);
        *(__half2*)&o.z = __floats2half2_rn(b.x, b.y);
        *(__half2*)&o.w = __floats2half2_rn(b.z, b.w);
        ((uint4*)xh)[t] = o;
    }
    if (t < E) atomicAdd(&cnt[ei[E + t]], 1);
}

// ---------------- CSR build ----------------
// 4 contiguous elems/thread via int4 (coalesced 16B/lane), 13 iterations.
__global__ __launch_bounds__(1024) void scan_kernel(int* __restrict__ cursor,
                                                    int* __restrict__ rowptr, int N) {
    __shared__ int warpsums[32];
    __shared__ int s_carry;
    int tid = threadIdx.x, lane = tid & 31, wid = tid >> 5;
    if (tid == 0) s_carry = 0;
    __syncthreads();
    for (int base = 0; base < N; base += 4096) {
        int i0 = base + tid * 4;
        int4 v;
        if (i0 + 3 < N) {
            v = *(const int4*)&cursor[i0];
        } else {
            v.x = (i0 < N) ? cursor[i0] : 0;
            v.y = (i0 + 1 < N) ? cursor[i0 + 1] : 0;
            v.z = (i0 + 2 < N) ? cursor[i0 + 2] : 0;
            v.w = (i0 + 3 < N) ? cursor[i0 + 3] : 0;
        }
        int tot = v.x + v.y + v.z + v.w;
        int x = tot;
        #pragma unroll
        for (int d = 1; d < 32; d <<= 1) {
            int y = __shfl_up_sync(0xffffffffu, x, d);
            if (lane >= d) x += y;
        }
        if (lane == 31) warpsums[wid] = x;
        __syncthreads();
        if (wid == 0) {
            int w = warpsums[lane];
            #pragma unroll
            for (int d = 1; d < 32; d <<= 1) {
                int y = __shfl_up_sync(0xffffffffu, w, d);
                if (lane >= d) w += y;
            }
            warpsums[lane] = w;
        }
        __syncthreads();
        int run = s_carry + ((wid > 0) ? warpsums[wid - 1] : 0) + (x - tot);
        int4 r;
        r.x = run; run += v.x;
        r.y = run; run += v.y;
        r.z = run; run += v.z;
        r.w = run;
        if (i0 + 3 < N) {
            *(int4*)&rowptr[i0] = r;
            *(int4*)&cursor[i0] = r;
        } else {
            if (i0 < N)     { rowptr[i0] = r.x;     cursor[i0] = r.x; }
            if (i0 + 1 < N) { rowptr[i0 + 1] = r.y; cursor[i0 + 1] = r.y; }
            if (i0 + 2 < N) { rowptr[i0 + 2] = r.z; cursor[i0 + 2] = r.z; }
            if (i0 + 3 < N) { rowptr[i0 + 3] = r.w; cursor[i0 + 3] = r.w; }
        }
        __syncthreads();
        if (tid == 0) s_carry += warpsums[31];
        __syncthreads();
    }
    if (threadIdx.x == 0) rowptr[N] = s_carry;
}

__global__ void fill_kernel(const int* __restrict__ ei, int* __restrict__ cursor,
                            int* __restrict__ csrc, int E) {
    int t = blockIdx.x * blockDim.x + threadIdx.x;
    if (t < E) {
        int d = ei[E + t];
        int p = atomicAdd(&cursor[d], 1);
        csrc[p] = ei[t] << 5;   // pre-scale: row offset in uint2 units
    }
}

// final output + restore invariants (cursor/gsum/gcnt/gridbar = 0)
__global__ void final_kernel(float* __restrict__ gsum, float* __restrict__ gcnt,
                             const float* __restrict__ fcb,
                             float* __restrict__ out, int G,
                             int* __restrict__ cursor, int N,
                             int* __restrict__ gridbar) {
    int i = blockIdx.x * blockDim.x + threadIdx.x;
    if (i < G) {
        out[i] = gsum[i] / fmaxf(gcnt[i], 1.0f) + fcb[0];
        gsum[i] = 0.f;
        gcnt[i] = 0.f;
    }
    if (i < N) cursor[i] = 0;
    if (i < 2) gridbar[i] = 0;
}

// ---------------- fused 3-layer aggregate+MLP (persistent, 1024 thr) ---------
#define SM_B1  0        // 34816
#define SM_B2  34816
#define SM_A   69632    // single fp16 A plane (also T after epilogue1)
#define SM_SB1 104448
#define SM_SB2 104960
#define SM_SFW 105472
#define SM_SROW 105984
#define SM_TOTAL 106496

// single-product fp16 GEMM: acc += A*B  (per-warp 16x32 tile)
__device__ __forceinline__ void gemm_tile(
    const __half* sA, const __half* sB,
    float acc[4][4], int wr, int wc, int lane) {
    int arow = wr * 16 + (lane & 15);
    int acol = (lane >> 4) * 8;
    int bn = wc * 32 + ((lane >> 4) << 3) + (lane & 7);
    int bk = ((lane >> 3) & 1) << 3;
    const __half* a_base = sA + arow * LDT + acol;
    const __half* b_base = sB + bn * LDT + bk;
    #pragma unroll
    for (int k0 = 0; k0 < 8; k0++) {
        uint32_t a[4];
        ldm4(a, smem_u32(a_base + k0 * 16));
        #pragma unroll
        for (int p = 0; p < 2; p++) {
            int nfp = p * 2;
            uint32_t b[4];
            ldm4(b, smem_u32(b_base + nfp * 8 * LDT + k0 * 16));
            mma16816(acc[nfp],     a, b[0], b[1]);
            mma16816(acc[nfp + 1], a, b[2], b[3]);
        }
    }
}

// accumulate 4 neighbor rows; pairwise fp16 adds, then fp32 accumulation
#define GATHER4H(v, J)                                                    \
    do {                                                                  \
        int o0 = __ldg(&csrc[(J)]);                                       \
        int o1 = __ldg(&csrc[(J) + 1]);                                   \
        int o2 = __ldg(&csrc[(J) + 2]);                                   \
        int o3 = __ldg(&csrc[(J) + 3]);                                   \
        uint2 w0 = Xh[o0 + lane];                                         \
        uint2 w1 = Xh[o1 + lane];                                         \
        uint2 w2 = Xh[o2 + lane];                                         \
        uint2 w3 = Xh[o3 + lane];                                         \
        __half2 p0 = __hadd2(*(__half2*)&w0.x, *(__half2*)&w1.x);         \
        __half2 p1 = __hadd2(*(__half2*)&w0.y, *(__half2*)&w1.y);         \
        __half2 p2 = __hadd2(*(__half2*)&w2.x, *(__half2*)&w3.x);         \
        __half2 p3 = __hadd2(*(__half2*)&w2.y, *(__half2*)&w3.y);         \
        float2 f;                                                         \
        f = __half22float2(p0); v.x += f.x; v.y += f.y;                   \
        f = __half22float2(p2); v.x += f.x; v.y += f.y;                   \
        f = __half22float2(p1); v.z += f.x; v.w += f.y;                   \
        f = __half22float2(p3); v.z += f.x; v.w += f.y;                   \
    } while (0)

__global__ __launch_bounds__(1024, 1) void mega_kernel(
    const __half* __restrict__ xh,
    const int* __restrict__ rowptr, const int* __restrict__ csrc,
    __half* __restrict__ bufA, __half* __restrict__ bufB,
    const __half* __restrict__ wth,
    const float* __restrict__ b1_0, const float* __restrict__ b1_1,
    const float* __restrict__ b1_2,
    const float* __restrict__ b2_0, const float* __restrict__ b2_1,
    const float* __restrict__ eps0, const float* __restrict__ eps1,
    const float* __restrict__ eps2,
    int n, int ntiles,
    const int* __restrict__ batch, const float* __restrict__ w2fc,
    float* __restrict__ gsum, float* __restrict__ gcnt) {
    extern __shared__ char sm[];
    __half* sB1 = (__half*)(sm + SM_B1);
    __half* sB2 = (__half*)(sm + SM_B2);
    __half* sA  = (__half*)(sm + SM_A);
    float* sb1  = (float*)(sm + SM_SB1);
    float* sb2  = (float*)(sm + SM_SB2);
    float* sfw  = (float*)(sm + SM_SFW);
    float* srow = (float*)(sm + SM_SROW);

    int tid = threadIdx.x;
    int lane = tid & 31;
    int wid = tid >> 5;
    int wr = wid & 7;
    int wc = wid >> 3;

    if (tid < 128) sfw[tid] = w2fc[tid];
    float bconst = __ldg(&w2fc[128]);

    #pragma unroll 1
    for (int l = 0; l < 3; l++) {
        int relu_out = (l < 2);
        int pool = (l == 2);
        const __half* X = (l == 0) ? xh : (l == 1) ? bufA : bufB;
        __half* H = (l == 0) ? bufA : bufB;
        const __half* W1 = wth + (2 * l) * 16384;
        const __half* W2 = wth + (2 * l + 1) * 16384;
        const float* b1 = (l == 0) ? b1_0 : (l == 1) ? b1_1 : b1_2;
        const float* b2 = (l == 0) ? b2_0 : b2_1;   // unused for l==2
        const float* epsp = (l == 0) ? eps0 : (l == 1) ? eps1 : eps2;

        if (tid < 128) {
            sb1[tid] = b1[tid];
            if (!pool) sb2[tid] = b2[tid];
        }
        // load weight planes (per layer)
        {
            const uint4* p1 = (const uint4*)W1;
            const uint4* p2 = (const uint4*)W2;
            for (int i = tid; i < 2048; i += 1024) {
                int r = i >> 4, c = (i & 15) * 8;
                int d = r * LDT + c;
                *(uint4*)&sB1[d] = p1[i];
                if (!pool) *(uint4*)&sB2[d] = p2[i];
            }
        }
        float s = 1.0f + __ldg(epsp);
        const uint2* Xh = (const uint2*)X;
        __syncthreads();

        for (int tile = blockIdx.x; tile < ntiles; tile += gridDim.x) {
            int row0 = tile * 128;
            if (tid < 128) srow[tid] = 0.f;

            // gather: A = (1+eps)*X[row] + sum_nbrs X[j]; 2 rows/warp iter
            for (int r2 = wid; r2 < 64; r2 += 32) {
                int rA = r2, rB = r2 + 64;
                int grA = row0 + rA, grB = row0 + rB;
                float4 va = make_float4(0.f, 0.f, 0.f, 0.f);
                float4 vb = make_float4(0.f, 0.f, 0.f, 0.f);
                int ja = 0, ea = 0, jb = 0, eb = 0;
                if (grA < n) {
                    uint2 w = Xh[grA * 32 + lane];
                    float2 f0 = __half22float2(*(__half2*)&w.x);
                    float2 f1 = __half22float2(*(__half2*)&w.y);
                    va.x = s * f0.x; va.y = s * f0.y;
                    va.z = s * f1.x; va.w = s * f1.y;
                    ja = __ldg(&rowptr[grA]); ea = __ldg(&rowptr[grA + 1]);
                }
                if (grB < n) {
                    uint2 w = Xh[grB * 32 + lane];
                    float2 f0 = __half22float2(*(__half2*)&w.x);
                    float2 f1 = __half22float2(*(__half2*)&w.y);
                    vb.x = s * f0.x; vb.y = s * f0.y;
                    vb.z = s * f1.x; vb.w = s * f1.y;
                    jb = __ldg(&rowptr[grB]); eb = __ldg(&rowptr[grB + 1]);
                }
                while (ja + 4 <= ea && jb + 4 <= eb) {
                    GATHER4H(va, ja);
                    GATHER4H(vb, jb);
                    ja += 4; jb += 4;
                }
                for (; ja + 4 <= ea; ja += 4) GATHER4H(va, ja);
                for (; ja < ea; ja++) {
                    int o0 = __ldg(&csrc[ja]);
                    uint2 w = Xh[o0 + lane];
                    float2 f0 = __half22float2(*(__half2*)&w.x);
                    float2 f1 = __half22float2(*(__half2*)&w.y);
                    va.x += f0.x; va.y += f0.y; va.z += f1.x; va.w += f1.y;
                }
                for (; jb + 4 <= eb; jb += 4) GATHER4H(vb, jb);
                for (; jb < eb; jb++) {
                    int o0 = __ldg(&csrc[jb]);
                    uint2 w = Xh[o0 + lane];
                    float2 f0 = __half22float2(*(__half2*)&w.x);
                    float2 f1 = __half22float2(*(__half2*)&w.y);
                    vb.x += f0.x; vb.y += f0.y; vb.z += f1.x; vb.w += f1.y;
                }
                uint2 o;
                *(__half2*)&o.x = __floats2half2_rn(va.x, va.y);
                *(__half2*)&o.y = __floats2half2_rn(va.z, va.w);
                *(uint2*)&sA[rA * LDT + lane * 4] = o;
                *(__half2*)&o.x = __floats2half2_rn(vb.x, vb.y);
                *(__half2*)&o.y = __floats2half2_rn(vb.z, vb.w);
                *(uint2*)&sA[rB * LDT + lane * 4] = o;
            }
            __syncthreads();

            float acc[4][4];
            #pragma unroll
            for (int j = 0; j < 4; j++)
                #pragma unroll
                for (int q = 0; q < 4; q++) acc[j][q] = 0.f;

            // GEMM1
            gemm_tile(sA, sB1, acc, wr, wc, lane);

            if (pool) {
                int r = wr * 16 + (lane >> 2);
                float d0 = 0.f, d1 = 0.f;
                #pragma unroll
                for (int nf = 0; nf < 4; nf++) {
                    int c = wc * 32 + nf * 8 + (lane & 3) * 2;
                    float* a = acc[nf];
                    d0 = fmaf(fmaxf(a[0] + sb1[c], 0.f), sfw[c], d0);
                    d0 = fmaf(fmaxf(a[1] + sb1[c + 1], 0.f), sfw[c + 1], d0);
                    d1 = fmaf(fmaxf(a[2] + sb1[c], 0.f), sfw[c], d1);
                    d1 = fmaf(fmaxf(a[3] + sb1[c + 1], 0.f), sfw[c + 1], d1);
                }
                atomicAdd(&srow[r], d0);
                atomicAdd(&srow[r + 8], d1);
                __syncthreads();
                if (tid < 128) {
                    int gr = row0 + tid;
                    if (gr < n) {
                        int g = batch[gr];
                        atomicAdd(&gsum[g], srow[tid] + bconst);
                        atomicAdd(&gcnt[g], 1.0f);
                    }
                }
                __syncthreads();
                continue;
            }

            __syncthreads();  // all reads of sA done before overwrite

            // epilogue1: T = ReLU(acc + b1) -> fp16 into sA
            {
                int r = wr * 16 + (lane >> 2);
                #pragma unroll
                for (int nf = 0; nf < 4; nf++) {
                    int c = wc * 32 + nf * 8 + (lane & 3) * 2;
                    float* a = acc[nf];
                    float v0 = fmaxf(a[0] + sb1[c], 0.f);
                    float v1 = fmaxf(a[1] + sb1[c + 1], 0.f);
                    float v2 = fmaxf(a[2] + sb1[c], 0.f);
                    float v3 = fmaxf(a[3] + sb1[c + 1], 0.f);
                    *(__half2*)&sA[r * LDT + c] = __floats2half2_rn(v0, v1);
                    *(__half2*)&sA[(r + 8) * LDT + c] = __floats2half2_rn(v2, v3);
                }
            }
            __syncthreads();

            #pragma unroll
            for (int j = 0; j < 4; j++)
                #pragma unroll
                for (int q = 0; q < 4; q++) acc[j][q] = 0.f;

            // GEMM2
            gemm_tile(sA, sB2, acc, wr, wc, lane);

            // epilogue2: out = acc + b2 (+ReLU) -> H (fp16)
            {
                int r = wr * 16 + (lane >> 2);
                int gr0 = row0 + r, gr1 = gr0 + 8;
                #pragma unroll
                for (int nf = 0; nf < 4; nf++) {
                    int c = wc * 32 + nf * 8 + (lane & 3) * 2;
                    float* a = acc[nf];
                    float v0 = a[0] + sb2[c], v1 = a[1] + sb2[c + 1];
                    float v2 = a[2] + sb2[c], v3 = a[3] + sb2[c + 1];
                    v0 = fmaxf(v0, 0.f); v1 = fmaxf(v1, 0.f);
                    v2 = fmaxf(v2, 0.f); v3 = fmaxf(v3, 0.f);
                    if (gr0 < n)
                        *(__half2*)&H[(size_t)gr0 * 128 + c] = __floats2half2_rn(v0, v1);
                    if (gr1 < n)
                        *(__half2*)&H[(size_t)gr1 * 128 + c] = __floats2half2_rn(v2, v3);
                }
            }
            __syncthreads();  // protect sA before next tile's gather
        }

        if (l < 2) grid_barrier(l);  // layer outputs visible grid-wide
    }
}

// ---------------- host launcher ----------------
extern "C" void kernel_launch(void* const* d_in, const int* in_sizes, int n_in,
                              void* d_out, int out_size) {
    const float* x     = (const float*)d_in[0];
    const int*   ei    = (const int*)d_in[1];
    const int*   batch = (const int*)d_in[2];
    const float* W1s[3] = {(const float*)d_in[3],  (const float*)d_in[8],  (const float*)d_in[13]};
    const float* b1s[3] = {(const float*)d_in[4],  (const float*)d_in[9],  (const float*)d_in[14]};
    const float* W2s[3] = {(const float*)d_in[5],  (const float*)d_in[10], (const float*)d_in[15]};
    const float* b2s[3] = {(const float*)d_in[6],  (const float*)d_in[11], (const float*)d_in[16]};
    const float* epss[3]= {(const float*)d_in[7],  (const float*)d_in[12], (const float*)d_in[17]};
    const float* fcw   = (const float*)d_in[18];
    const float* fcb   = (const float*)d_in[19];

    int N = in_sizes[2];
    int E = in_sizes[1] / 2;
    int G = out_size;

    float *gsum, *gcnt, *w2fc;
    __half *xh, *bufA, *bufB, *wth;
    int *rowptr, *cursor, *csrc, *gridbar;
    cudaGetSymbolAddress((void**)&xh,   g_xh);
    cudaGetSymbolAddress((void**)&bufA, g_bufA);
    cudaGetSymbolAddress((void**)&bufB, g_bufB);
    cudaGetSymbolAddress((void**)&gsum, g_gsum);
    cudaGetSymbolAddress((void**)&gcnt, g_gcnt);
    cudaGetSymbolAddress((void**)&rowptr, g_rowptr);
    cudaGetSymbolAddress((void**)&cursor, g_cursor);
    cudaGetSymbolAddress((void**)&csrc, g_csrc);
    cudaGetSymbolAddress((void**)&w2fc, g_w2fc);
    cudaGetSymbolAddress((void**)&wth,  g_wth);
    cudaGetSymbolAddress((void**)&gridbar, g_gridbar);

    cudaFuncSetAttribute(mega_kernel, cudaFuncAttributeMaxDynamicSharedMemorySize, SM_TOTAL);

    int prep_threads = E;
    if (N * 16 > prep_threads) prep_threads = N * 16;
    if (6 * 16384 + 129 > prep_threads) prep_threads = 6 * 16384 + 129;
    // 1: weight transform + x->fp16 + edge count + w2fc (cursor==0 at entry)
    prep_kernel<<<(prep_threads + 255) / 256, 256>>>(
        W1s[0], W2s[0], W1s[1], W2s[1], W1s[2], W2s[2],
        wth, x, xh, N, ei, cursor, E, fcw, b2s[2], w2fc);
    // 2-3: CSR scan + fill (pre-scaled offsets)
    scan_kernel<<<1, 1024>>>(cursor, rowptr, N);
    fill_kernel<<<(E + 255) / 256, 256>>>(ei, cursor, csrc, E);

    // 4: fused 3-layer MLP (persistent, grid barriers between layers)
    int ntiles = (N + 127) / 128;
    mega_kernel<<<148, 1024, SM_TOTAL>>>(
        xh, rowptr, csrc, bufA, bufB, wth,
        b1s[0], b1s[1], b1s[2], b2s[0], b2s[1],
        epss[0], epss[1], epss[2],
        N, ntiles, batch, w2fc, gsum, gcnt);

    // 5: output + restore invariants (cursor/gsum/gcnt/gridbar -> 0)
    final_kernel<<<(N + 255) / 256, 256>>>(gsum, gcnt, fcb, (float*)d_out, G,
                                           cursor, N, gridbar);
}